// round 15
// baseline (speedup 1.0000x reference)
#include <cuda_runtime.h>
#include <cuda_fp16.h>
#include <cstdint>
#include <cstddef>

// ===========================================================================
// GCN via mma.sync f16 tensor cores, fp32 accumulators.
// R15: wave-quantization fix — the six 512-CTA launches (L3P/L3d/L4d/cls +
// L1/L3/L4 agg) move to M=64 tiles (template MT=2): 1024 CTAs at half
// per-CTA time (~3.5 waves vs ~4), MT=2 agg also fits 2 CTAs/SM.
// Per-output-element accumulation order bitwise-identical to R14.
// ===========================================================================

#define BATCH 32
#define SEQ   1024

// ---------------- device scratch (allocation-free rule) --------------------
__device__ __half g_adjh[33554432];
__device__ __half g_Uh[16777216];
__device__ __half g_Vh[16777216];
__device__ __half g_Gh[16777216];
__device__ __half g_Ph[8388608];
__device__ __half g_Wh[1245184], g_Wl[1245184];
__device__ float  g_rmV[32768], g_rmG[32768];
__device__ float  g_csT[512], g_csB[512];

// ---------------- PTX helpers ----------------------------------------------
__device__ __forceinline__ uint32_t smem_u32(const void* p) {
    uint32_t a;
    asm("{ .reg .u64 t; cvta.to.shared.u64 t, %1; cvt.u32.u64 %0, t; }"
        : "=r"(a) : "l"(p));
    return a;
}
__device__ __forceinline__ void cp_async16(uint32_t dst, const void* src) {
    asm volatile("cp.async.cg.shared.global [%0], [%1], 16;"
                 :: "r"(dst), "l"(src));
}
#define CP_COMMIT() asm volatile("cp.async.commit_group;" ::: "memory")
#define CP_WAIT1()  asm volatile("cp.async.wait_group 1;" ::: "memory")
#define CP_WAIT0()  asm volatile("cp.async.wait_group 0;" ::: "memory")

__device__ __forceinline__ void ldsm4(uint32_t* d, uint32_t a) {
    asm volatile("ldmatrix.sync.aligned.m8n8.x4.shared.b16 {%0,%1,%2,%3}, [%4];"
                 : "=r"(d[0]), "=r"(d[1]), "=r"(d[2]), "=r"(d[3]) : "r"(a));
}
__device__ __forceinline__ void ldsm4t(uint32_t* d, uint32_t a) {
    asm volatile("ldmatrix.sync.aligned.m8n8.x4.trans.shared.b16 {%0,%1,%2,%3}, [%4];"
                 : "=r"(d[0]), "=r"(d[1]), "=r"(d[2]), "=r"(d[3]) : "r"(a));
}
__device__ __forceinline__ void mma16816(float* c, const uint32_t* a,
                                         uint32_t b0, uint32_t b1) {
    asm volatile(
        "mma.sync.aligned.m16n8k16.row.col.f32.f16.f16.f32 "
        "{%0,%1,%2,%3}, {%4,%5,%6,%7}, {%8,%9}, {%0,%1,%2,%3};"
        : "+f"(c[0]), "+f"(c[1]), "+f"(c[2]), "+f"(c[3])
        : "r"(a[0]), "r"(a[1]), "r"(a[2]), "r"(a[3]), "r"(b0), "r"(b1));
}

// ---------------- BK=128 smem layout ----------------------------------------
#define T_STRIDE  272                  // 128 f16 = 256B + 16B pad
// Tile M = MT*32 (MT = 16-row subtiles per warp; 2 M-warp-groups).
// Per-stage: A = MT*32*272 ; Bh = 34816 ; Bl = 34816 (terms==2)

// ---------------------------------------------------------------------------
// Unified dense f16 GEMM (BK=128, 2-stage). (MT*32)x128 output tile.
//   terms==1: A*Bh ; terms==2: A*Bh + A*Bl (per 16-k slice: hi then lo)
//   pass0: A0 x B0 ; pass1 (K1>0): + A1 x B1   (concat GEMM)
//   epilogue: + rank-1 + f16 addend + bias, act 0/1/2, f16 out.
// ---------------------------------------------------------------------------
template<int MT>
__global__ __launch_bounds__(256, 1) void gemm_dense(
    const __half* __restrict__ A0, int lda0, int K0,
    const __half* __restrict__ B0h, const __half* __restrict__ B0l, int ldb0,
    const __half* __restrict__ A1, int lda1, int K1,
    const __half* __restrict__ B1h, const __half* __restrict__ B1l, int ldb1,
    int terms,
    const float* __restrict__ rm0, const float* __restrict__ cs0,
    const float* __restrict__ rm1, const float* __restrict__ cs1,
    const __half* __restrict__ addendH,
    const float* __restrict__ bias, const float* __restrict__ alphaP, int act,
    __half* __restrict__ outH, int Nd)
{
    constexpr int DBH_OFF = MT * 32 * T_STRIDE;
    constexpr int DBL_OFF = DBH_OFF + 34816;
    extern __shared__ char smem[];
    const uint32_t sb = smem_u32(smem);
    const int tid  = threadIdx.x;
    const int wid  = tid >> 5, lane = tid & 31;
    const int colBlock = blockIdx.x * 128;
    const size_t gRow0 = (size_t)blockIdx.y * (MT * 32);

    const __half* a0 = A0 + gRow0 * lda0;
    const __half* a1 = A1 ? A1 + gRow0 * lda1 : nullptr;

    const int stageSz = DBH_OFF + ((terms == 2) ? 69632 : 34816);
    const int n0 = K0 >> 7;
    const int nChunks = n0 + (K1 >> 7);

    auto issue_loads = [&](int c) {
        const uint32_t so = sb + (c & 1) * stageSz;
        const int pass = (c < n0) ? 0 : 1;
        const int k0 = (pass ? (c - n0) : c) << 7;
        const __half* aP = pass ? a1 : a0;
        const __half* bH = pass ? B1h : B0h;
        const __half* bL = pass ? B1l : B0l;
        const int lA = pass ? lda1 : lda0;
        const int lB = pass ? ldb1 : ldb0;
        #pragma unroll
        for (int i = 0; i < 2 * MT; i++) {
            const int idx = tid + i * 256;
            const int r = idx >> 4, cc = idx & 15;
            cp_async16(so + r * T_STRIDE + cc * 16,
                       aP + (size_t)r * lA + k0 + cc * 8);
        }
        #pragma unroll
        for (int i = 0; i < 8; i++) {
            const int idx = tid + i * 256;
            const int r = idx >> 4, cc = idx & 15;
            const size_t gsrc = (size_t)(k0 + r) * lB + colBlock + cc * 8;
            cp_async16(so + DBH_OFF + r * T_STRIDE + cc * 16, bH + gsrc);
            if (terms == 2)
                cp_async16(so + DBL_OFF + r * T_STRIDE + cc * 16, bL + gsrc);
        }
        CP_COMMIT();
    };

    float acc[MT][4][4];
    #pragma unroll
    for (int i = 0; i < MT; i++)
        #pragma unroll
        for (int j = 0; j < 4; j++)
            #pragma unroll
            for (int q = 0; q < 4; q++) acc[i][j][q] = 0.0f;

    issue_loads(0);

    const int warpM = wid >> 2;
    const int warpN = wid & 3;
    const int mBase = warpM * (MT * 16);
    const int nBase = warpN * 32;
    const int lr  = lane & 15;
    const int lc8 = (lane >> 4) * 8;

    for (int c = 0; c < nChunks; c++) {
        if (c + 1 < nChunks) { issue_loads(c + 1); CP_WAIT1(); }
        else                 { CP_WAIT0(); }
        __syncthreads();
        const uint32_t so = sb + (c & 1) * stageSz;

        #pragma unroll
        for (int kt = 0; kt < 8; kt++) {
            const int kb = kt * 16;
            uint32_t af[MT][4], bh[2][4], bl[2][4];
            #pragma unroll
            for (int mt = 0; mt < MT; mt++)
                ldsm4(af[mt], so +
                      (mBase + mt * 16 + lr) * T_STRIDE + (kb + lc8) * 2);
            #pragma unroll
            for (int nb = 0; nb < 2; nb++) {
                const uint32_t bd = so + DBH_OFF +
                    (kb + lr) * T_STRIDE + (nBase + nb * 16 + lc8) * 2;
                ldsm4t(bh[nb], bd);
                if (terms == 2) ldsm4t(bl[nb], bd + (DBL_OFF - DBH_OFF));
            }
            #pragma unroll
            for (int mt = 0; mt < MT; mt++)
                #pragma unroll
                for (int n8 = 0; n8 < 4; n8++) {
                    const int nb = n8 >> 1, w = (n8 & 1) * 2;
                    mma16816(acc[mt][n8], af[mt], bh[nb][w], bh[nb][w + 1]);
                }
            if (terms == 2) {
                #pragma unroll
                for (int mt = 0; mt < MT; mt++)
                    #pragma unroll
                    for (int n8 = 0; n8 < 4; n8++) {
                        const int nb = n8 >> 1, w = (n8 & 1) * 2;
                        mma16816(acc[mt][n8], af[mt], bl[nb][w], bl[nb][w + 1]);
                    }
            }
        }
        __syncthreads();
    }

    // ---------------- epilogue ----------------------------------------------
    #pragma unroll
    for (int mt = 0; mt < MT; mt++) {
        #pragma unroll
        for (int half = 0; half < 2; half++) {
            const size_t grow = gRow0 + mBase + mt * 16 + (lane >> 2) + half * 8;
            const float r0 = rm0 ? rm0[grow] : 0.0f;
            const float r1 = rm1 ? rm1[grow] : 0.0f;
            #pragma unroll
            for (int n8 = 0; n8 < 4; n8++) {
                const int col = colBlock + nBase + n8 * 8 + 2 * (lane & 3);
                float v0 = acc[mt][n8][half * 2 + 0];
                float v1 = acc[mt][n8][half * 2 + 1];
                if (rm0) {
                    v0 += r0 * cs0[col] + r1 * cs1[col];
                    v1 += r0 * cs0[col + 1] + r1 * cs1[col + 1];
                }
                if (addendH) {
                    __half2 ad = *reinterpret_cast<const __half2*>(
                        addendH + grow * Nd + col);
                    v0 += __half2float(ad.x);
                    v1 += __half2float(ad.y);
                }
                if (bias) { v0 += bias[col]; v1 += bias[col + 1]; }
                if (act == 1) {
                    v0 = fmaxf(v0, 0.0f); v1 = fmaxf(v1, 0.0f);
                } else if (act == 2) {
                    v0 = (v0 > 0.0f) ? v0 : alphaP[col] * v0;
                    v1 = (v1 > 0.0f) ? v1 : alphaP[col + 1] * v1;
                }
                *reinterpret_cast<__half2*>(outH + grow * Nd + col) =
                    __halves2half2(__float2half_rn(v0), __float2half_rn(v1));
            }
        }
    }
}

// ---------------------------------------------------------------------------
// 1-term plain f16 GEMM (aggregation): (MT*32)x128 tile, BK=128, 2-stage.
// A = adj tile (row-major, batched z), B = h. Writes hi plane only.
// ---------------------------------------------------------------------------
template<int MT>
__global__ __launch_bounds__(256) void gemm_agg(
    const __half* __restrict__ A, size_t aB, int lda, int K,
    const __half* __restrict__ B, size_t bB, int ldb,
    __half* __restrict__ outH, int Nd)
{
    constexpr int DBH_OFF = MT * 32 * T_STRIDE;
    constexpr int STG = DBH_OFF + 34816;
    extern __shared__ char smem[];
    const uint32_t sb = smem_u32(smem);
    const int tid  = threadIdx.x;
    const int wid  = tid >> 5, lane = tid & 31;
    const int z    = blockIdx.z;
    const int colBlock = blockIdx.x * 128;
    const size_t gRow0 = (size_t)z * SEQ + (size_t)blockIdx.y * (MT * 32);

    const __half* aP = A + z * aB + (size_t)(blockIdx.y * (MT * 32)) * lda;
    const __half* bP = B + z * bB;

    const int nChunks = K >> 7;

    auto issue_loads = [&](int c) {
        const uint32_t so = sb + (c & 1) * STG;
        const int k0 = c << 7;
        #pragma unroll
        for (int i = 0; i < 2 * MT; i++) {
            const int idx = tid + i * 256;
            const int r = idx >> 4, cc = idx & 15;
            cp_async16(so + r * T_STRIDE + cc * 16,
                       aP + (size_t)r * lda + k0 + cc * 8);
        }
        #pragma unroll
        for (int i = 0; i < 8; i++) {
            const int idx = tid + i * 256;
            const int r = idx >> 4, cc = idx & 15;
            cp_async16(so + DBH_OFF + r * T_STRIDE + cc * 16,
                       bP + (size_t)(k0 + r) * ldb + colBlock + cc * 8);
        }
        CP_COMMIT();
    };

    float acc[MT][4][4];
    #pragma unroll
    for (int i = 0; i < MT; i++)
        #pragma unroll
        for (int j = 0; j < 4; j++)
            #pragma unroll
            for (int q = 0; q < 4; q++) acc[i][j][q] = 0.0f;

    issue_loads(0);

    const int warpM = wid >> 2;
    const int warpN = wid & 3;
    const int mBase = warpM * (MT * 16);
    const int nBase = warpN * 32;
    const int lr  = lane & 15;
    const int lc8 = (lane >> 4) * 8;

    for (int c = 0; c < nChunks; c++) {
        if (c + 1 < nChunks) { issue_loads(c + 1); CP_WAIT1(); }
        else                 { CP_WAIT0(); }
        __syncthreads();
        const uint32_t so = sb + (c & 1) * STG;

        #pragma unroll
        for (int kt = 0; kt < 8; kt++) {
            const int kb = kt * 16;
            uint32_t af[MT][4], bf[2][4];
            #pragma unroll
            for (int mt = 0; mt < MT; mt++)
                ldsm4(af[mt], so +
                      (mBase + mt * 16 + lr) * T_STRIDE + (kb + lc8) * 2);
            #pragma unroll
            for (int nb = 0; nb < 2; nb++)
                ldsm4t(bf[nb], so + DBH_OFF +
                       (kb + lr) * T_STRIDE + (nBase + nb * 16 + lc8) * 2);
            #pragma unroll
            for (int mt = 0; mt < MT; mt++)
                #pragma unroll
                for (int n8 = 0; n8 < 4; n8++) {
                    const int nb = n8 >> 1, w = (n8 & 1) * 2;
                    mma16816(acc[mt][n8], af[mt], bf[nb][w], bf[nb][w + 1]);
                }
        }
        __syncthreads();
    }

    #pragma unroll
    for (int mt = 0; mt < MT; mt++) {
        #pragma unroll
        for (int half = 0; half < 2; half++) {
            const size_t grow = gRow0 + mBase + mt * 16 + (lane >> 2) + half * 8;
            #pragma unroll
            for (int n8 = 0; n8 < 4; n8++) {
                const int col = colBlock + nBase + n8 * 8 + 2 * (lane & 3);
                *reinterpret_cast<__half2*>(outH + grow * Nd + col) =
                    __halves2half2(__float2half_rn(acc[mt][n8][half * 2 + 0]),
                                   __float2half_rn(acc[mt][n8][half * 2 + 1]));
            }
        }
    }
}

// ---------------------------------------------------------------------------
__global__ void split_hi(const float* __restrict__ in,
                         __half* __restrict__ h, int n4)
{
    for (int i = blockIdx.x * blockDim.x + threadIdx.x; i < n4;
         i += gridDim.x * blockDim.x) {
        float4 v = reinterpret_cast<const float4*>(in)[i];
        __half hh[4] = {
            __float2half_rn(v.x), __float2half_rn(v.y),
            __float2half_rn(v.z), __float2half_rn(v.w) };
        *reinterpret_cast<uint2*>(h + (size_t)i * 4) = *reinterpret_cast<uint2*>(hh);
    }
}

__global__ void split_w_all(
    const float* __restrict__ s0, const float* __restrict__ s1,
    const float* __restrict__ s2, const float* __restrict__ s3,
    const float* __restrict__ s4,
    __half* __restrict__ Wh, __half* __restrict__ Wl)
{
    for (int i = blockIdx.x * blockDim.x + threadIdx.x; i < 311296;
         i += gridDim.x * blockDim.x) {
        const float* src; size_t dst; int j = i;
        if (j < 65536)        { src = s0; dst = 0;       }
        else if (j < 196608)  { src = s1; dst = 262144; j -= 65536;  }
        else if (j < 262144)  { src = s2; dst = 786432; j -= 196608; }
        else if (j < 294912)  { src = s3; dst = 1048576; j -= 262144; }
        else                  { src = s4; dst = 1179648; j -= 294912; }
        float4 v = reinterpret_cast<const float4*>(src)[j];
        float vv[4] = {v.x, v.y, v.z, v.w};
        __half hh[4], ll[4];
        #pragma unroll
        for (int q = 0; q < 4; q++) {
            hh[q] = __float2half_rn(vv[q]);
            ll[q] = __float2half_rn(vv[q] - __half2float(hh[q]));
        }
        *reinterpret_cast<uint2*>(Wh + dst + (size_t)j * 4) = *reinterpret_cast<uint2*>(hh);
        *reinterpret_cast<uint2*>(Wl + dst + (size_t)j * 4) = *reinterpret_cast<uint2*>(ll);
    }
}

__global__ __launch_bounds__(256) void rowmean_kernel(
    const __half* __restrict__ T, float* __restrict__ rm, int M, int Nd)
{
    const int row = (blockIdx.x * blockDim.x + threadIdx.x) >> 5;
    const int lane = threadIdx.x & 31;
    if (row >= M) return;
    const __half* p = T + (size_t)row * Nd;
    float s = 0.0f;
    for (int j = lane; j < Nd; j += 32) s += __half2float(p[j]);
    #pragma unroll
    for (int off = 16; off > 0; off >>= 1)
        s += __shfl_down_sync(0xFFFFFFFFu, s, off);
    if (lane == 0) rm[row] = s * (1.0f / Nd);
}

__global__ __launch_bounds__(256) void colsum_kernel(
    const __half* __restrict__ W2l, float* __restrict__ csT,
    float* __restrict__ csB)
{
    const int gw = (blockIdx.x * 256 + threadIdx.x) >> 5;
    const int lane = threadIdx.x & 31;
    if (gw >= 1024) return;
    const int halfSel = gw >> 9;
    const int j = gw & 511;
    const int k0 = halfSel << 9;
    float s = 0.0f;
    #pragma unroll
    for (int kk = 0; kk < 512; kk += 32)
        s += __half2float(W2l[(size_t)(k0 + kk + lane) * 512 + j]);
    #pragma unroll
    for (int off = 16; off > 0; off >>= 1)
        s += __shfl_down_sync(0xFFFFFFFFu, s, off);
    if (lane == 0) (halfSel ? csB : csT)[j] = s;
}

__global__ __launch_bounds__(256) void head_kernel(
    const __half* __restrict__ T, const float* __restrict__ W,
    const float* __restrict__ bvec, float* __restrict__ out, int M)
{
    const int warp = (blockIdx.x * blockDim.x + threadIdx.x) >> 5;
    const int lane = threadIdx.x & 31;
    if (warp >= M) return;
    const __half* row = T + (size_t)warp * 256;
    float s0 = 0.0f, s1 = 0.0f;
    #pragma unroll
    for (int j0 = 0; j0 < 256; j0 += 32) {
        const float v = __half2float(row[j0 + lane]);
        s0 = fmaf(v, W[(j0 + lane) * 2 + 0], s0);
        s1 = fmaf(v, W[(j0 + lane) * 2 + 1], s1);
    }
    #pragma unroll
    for (int off = 16; off > 0; off >>= 1) {
        s0 += __shfl_down_sync(0xFFFFFFFFu, s0, off);
        s1 += __shfl_down_sync(0xFFFFFFFFu, s1, off);
    }
    if (lane == 0) {
        out[(size_t)warp * 2 + 0] = s0 + bvec[0];
        out[(size_t)warp * 2 + 1] = s1 + bvec[1];
    }
}

// ---------------------------------------------------------------------------
extern "C" void kernel_launch(void* const* d_in, const int* in_sizes, int n_in,
                              void* d_out, int out_size)
{
    (void)in_sizes; (void)n_in; (void)out_size;
    const float* x     = (const float*)d_in[0];
    const float* adj   = (const float*)d_in[1];
    const float* W1    = (const float*)d_in[2];
    const float* b1    = (const float*)d_in[3];
    const float* W2    = (const float*)d_in[4];
    const float* b2    = (const float*)d_in[5];
    const float* W3    = (const float*)d_in[6];
    const float* b3    = (const float*)d_in[7];
    const float* W4    = (const float*)d_in[8];
    const float* b4    = (const float*)d_in[9];
    const float* cW1   = (const float*)d_in[10];
    const float* cb1   = (const float*)d_in[11];
    const float* alpha = (const float*)d_in[12];
    const float* cW2   = (const float*)d_in[13];
    const float* cb2   = (const float*)d_in[14];
    float* out = (float*)d_out;

    __half *adjh, *Uh, *Vh, *Gh, *Ph, *Wh, *Wl;
    float *rmV, *rmG, *csT, *csB;
    cudaGetSymbolAddress((void**)&adjh, g_adjh);
    cudaGetSymbolAddress((void**)&Uh, g_Uh);
    cudaGetSymbolAddress((void**)&Vh, g_Vh);
    cudaGetSymbolAddress((void**)&Gh, g_Gh);
    cudaGetSymbolAddress((void**)&Ph, g_Ph);
    cudaGetSymbolAddress((void**)&Wh, g_Wh);
    cudaGetSymbolAddress((void**)&Wl, g_Wl);
    cudaGetSymbolAddress((void**)&rmV, g_rmV);
    cudaGetSymbolAddress((void**)&rmG, g_rmG);
    cudaGetSymbolAddress((void**)&csT, g_csT);
    cudaGetSymbolAddress((void**)&csB, g_csB);

    // smem sizes: dense<4> 2t: (34816+69632)*2 = 208896 ; dense<2> 2t: 174080
    // dense<4> 1t: 139264 ; agg<4>: 139264 ; agg<2>: 104448
    cudaFuncSetAttribute(gemm_dense<4>,
        cudaFuncAttributeMaxDynamicSharedMemorySize, 208896);
    cudaFuncSetAttribute(gemm_dense<2>,
        cudaFuncAttributeMaxDynamicSharedMemorySize, 174080);
    cudaFuncSetAttribute(gemm_agg<4>,
        cudaFuncAttributeMaxDynamicSharedMemorySize, 139264);
    cudaFuncSetAttribute(gemm_agg<2>,
        cudaFuncAttributeMaxDynamicSharedMemorySize, 104448);
    dim3 blk(256);

    // ---- conversions ----
    split_hi<<<4096, blk>>>(adj, adjh, 8388608);
    split_hi<<<1024, blk>>>(x, Uh, 2097152);
    split_w_all<<<1216, blk>>>(W1, W2, W3, W4, cW1, Wh, Wl);
    colsum_kernel<<<128, blk>>>(Wl + 262144, csT, csB);

    const size_t ADJB = 1048576;
    const int M = BATCH * SEQ;

    // ---- Layer 1 (256 -> 512): agg 1-term (MT=2); dense 2-term (MT=4) ----
    gemm_agg<2><<<dim3(2, 16, 32), blk, 104448>>>(
        adjh, ADJB, 1024, 1024, Uh, (size_t)1024 * 256, 256, Gh, 256);
    gemm_dense<4><<<dim3(4, 256), blk, 208896>>>(
        Uh, 256, 256, Wh, Wl, 512,
        Gh, 256, 256, Wh + 131072, Wl + 131072, 512, 2,
        nullptr, nullptr, nullptr, nullptr, nullptr,
        b1, nullptr, 1, Vh, 512);

    // ---- Layer 2 (512 -> 512): dense 1-term (MT=4) + rank-1 compensation ----
    rowmean_kernel<<<4096, blk>>>(Vh, rmV, M, 512);
    gemm_agg<4><<<dim3(4, 8, 32), blk, 139264>>>(
        adjh, ADJB, 1024, 1024, Vh, (size_t)1024 * 512, 512, Gh, 512);
    rowmean_kernel<<<4096, blk>>>(Gh, rmG, M, 512);
    gemm_dense<4><<<dim3(4, 256), blk, 139264>>>(
        Vh, 512, 512, Wh + 262144, nullptr, 512,
        Gh, 512, 512, Wh + 524288, nullptr, 512, 1,
        rmV, csT, rmG, csB, nullptr,
        b2, nullptr, 1, Uh, 512);

    // ---- Layer 3 (512 -> 256), reassociated (all MT=2):
    //   P = h2@Wb3 (2t) ; G3 = adj@P (1t, N=256) ; h3 = relu(h2@Wt3 + G3 + b3)
    gemm_dense<2><<<dim3(2, 512), blk, 174080>>>(
        Uh, 512, 512, Wh + 917504, Wl + 917504, 256,
        nullptr, 0, 0, nullptr, nullptr, 0, 2,
        nullptr, nullptr, nullptr, nullptr, nullptr,
        nullptr, nullptr, 0, Ph, 256);
    gemm_agg<2><<<dim3(2, 16, 32), blk, 104448>>>(
        adjh, ADJB, 1024, 1024, Ph, (size_t)1024 * 256, 256, Gh, 256);
    gemm_dense<2><<<dim3(2, 512), blk, 174080>>>(
        Uh, 512, 512, Wh + 786432, Wl + 786432, 256,
        nullptr, 0, 0, nullptr, nullptr, 0, 2,
        nullptr, nullptr, nullptr, nullptr, Gh,
        b3, nullptr, 1, Vh, 256);

    // ---- Layer 4 (256 -> 256): agg (MT=2); dense 2-term (MT=2) ----
    gemm_agg<2><<<dim3(2, 16, 32), blk, 104448>>>(
        adjh, ADJB, 1024, 1024, Vh, (size_t)1024 * 256, 256, Gh, 256);
    gemm_dense<2><<<dim3(2, 512), blk, 174080>>>(
        Vh, 256, 256, Wh + 1048576, Wl + 1048576, 256,
        Gh, 256, 256, Wh + 1114112, Wl + 1114112, 256, 2,
        nullptr, nullptr, nullptr, nullptr, nullptr,
        b4, nullptr, 1, Uh, 256);

    // ---- classifier: Linear + PReLU 2-term (MT=2), then 256->2 head ----
    gemm_dense<2><<<dim3(2, 512), blk, 174080>>>(
        Uh, 256, 256, Wh + 1179648, Wl + 1179648, 256,
        nullptr, 0, 0, nullptr, nullptr, 0, 2,
        nullptr, nullptr, nullptr, nullptr, nullptr,
        cb1, alpha, 2, Vh, 256);
    head_kernel<<<(M * 32 + 255) / 256, blk>>>(Vh, cW2, cb2, out, M);
}